// round 5
// baseline (speedup 1.0000x reference)
#include <cuda_runtime.h>
#include <cuda_fp16.h>
#include <math.h>

#define NN 100000
#define EE 1600000
#define FD 128
#define HD 64

typedef unsigned long long ull;

// Scratch (device globals)
__device__ int    g_cnt[2 * NN + 32];       // [0..NN)=out, [NN..2NN)=in, [2NN]=scan ticket
__device__ float  g_nsrc[NN];
__device__ float  g_ndst[NN];
__device__ int    g_off[NN];
__device__ int    g_cursor[NN];
__device__ int    g_csr[EE];
__device__ __half g_x16[(size_t)NN * HD];
__device__ __half g_y16[(size_t)NN * HD];

// ---------------------------------------------------------------------------
// Packed fp32x2 helpers (Blackwell FFMA2)
// ---------------------------------------------------------------------------
__device__ __forceinline__ ull f2pack(float lo, float hi) {
    ull r;
    asm("mov.b64 %0, {%1, %2};" : "=l"(r) : "f"(lo), "f"(hi));
    return r;
}
__device__ __forceinline__ void f2fma(ull& d, ull a, ull b) {
    asm("fma.rn.f32x2 %0, %1, %2, %0;" : "+l"(d) : "l"(a), "l"(b));
}
__device__ __forceinline__ float2 f2unpack(ull v) {
    float lo, hi;
    asm("mov.b64 {%0, %1}, %2;" : "=f"(lo), "=f"(hi) : "l"(v));
    return make_float2(lo, hi);
}

// ---------------------------------------------------------------------------
// Degrees: 8 edges per thread (MLP for ATOMG latency)
// ---------------------------------------------------------------------------
__global__ void deg_kernel(const int* __restrict__ src, const int* __restrict__ dst, int E) {
    int i = (blockIdx.x * blockDim.x + threadIdx.x) * 8;
    if (i + 8 <= E) {
        int4 s0 = *(const int4*)(src + i);
        int4 s1 = *(const int4*)(src + i + 4);
        int4 d0 = *(const int4*)(dst + i);
        int4 d1 = *(const int4*)(dst + i + 4);
        atomicAdd(&g_cnt[s0.x], 1); atomicAdd(&g_cnt[s0.y], 1);
        atomicAdd(&g_cnt[s0.z], 1); atomicAdd(&g_cnt[s0.w], 1);
        atomicAdd(&g_cnt[s1.x], 1); atomicAdd(&g_cnt[s1.y], 1);
        atomicAdd(&g_cnt[s1.z], 1); atomicAdd(&g_cnt[s1.w], 1);
        atomicAdd(&g_cnt[NN + d0.x], 1); atomicAdd(&g_cnt[NN + d0.y], 1);
        atomicAdd(&g_cnt[NN + d0.z], 1); atomicAdd(&g_cnt[NN + d0.w], 1);
        atomicAdd(&g_cnt[NN + d1.x], 1); atomicAdd(&g_cnt[NN + d1.y], 1);
        atomicAdd(&g_cnt[NN + d1.z], 1); atomicAdd(&g_cnt[NN + d1.w], 1);
    } else {
        for (int j = i; j < E; j++) {
            atomicAdd(&g_cnt[src[j]], 1);
            atomicAdd(&g_cnt[NN + dst[j]], 1);
        }
    }
}

// ---------------------------------------------------------------------------
// Scan + norm fused (segments disjoint, unordered: block base via atomic ticket)
// ---------------------------------------------------------------------------
__global__ void __launch_bounds__(256) scan_norm_kernel(int N) {
    __shared__ int wsum[8];
    __shared__ int sbase;
    int i = blockIdx.x * 256 + threadIdx.x;
    int lane = threadIdx.x & 31, wid = threadIdx.x >> 5;

    int cin = (i < N) ? g_cnt[NN + i] : 0;
    int x = cin;
#pragma unroll
    for (int o = 1; o < 32; o <<= 1) {
        int n = __shfl_up_sync(0xffffffffu, x, o);
        if (lane >= o) x += n;
    }
    if (lane == 31) wsum[wid] = x;
    __syncthreads();
    if (threadIdx.x == 0) {
        int run = 0;
#pragma unroll
        for (int w = 0; w < 8; w++) { run += wsum[w]; wsum[w] = run; }
        sbase = atomicAdd(&g_cnt[2 * NN], run);
    }
    __syncthreads();
    int excl = x - cin + (wid > 0 ? wsum[wid - 1] : 0) + sbase;
    if (i < N) {
        g_off[i] = excl;
        g_cursor[i] = excl;
        g_nsrc[i] = rsqrtf(fmaxf((float)g_cnt[i], 1.0f));
        g_ndst[i] = rsqrtf(fmaxf((float)cin, 1.0f));
    }
}

// ---------------------------------------------------------------------------
// Fill CSR: 8 edges per thread
// ---------------------------------------------------------------------------
__global__ void fill_kernel(const int* __restrict__ src, const int* __restrict__ dst, int E) {
    int i = (blockIdx.x * blockDim.x + threadIdx.x) * 8;
    if (i + 8 <= E) {
        int4 d0 = *(const int4*)(dst + i);
        int4 d1 = *(const int4*)(dst + i + 4);
        int4 s0 = *(const int4*)(src + i);
        int4 s1 = *(const int4*)(src + i + 4);
        int p0 = atomicAdd(&g_cursor[d0.x], 1);
        int p1 = atomicAdd(&g_cursor[d0.y], 1);
        int p2 = atomicAdd(&g_cursor[d0.z], 1);
        int p3 = atomicAdd(&g_cursor[d0.w], 1);
        int p4 = atomicAdd(&g_cursor[d1.x], 1);
        int p5 = atomicAdd(&g_cursor[d1.y], 1);
        int p6 = atomicAdd(&g_cursor[d1.z], 1);
        int p7 = atomicAdd(&g_cursor[d1.w], 1);
        g_csr[p0] = s0.x; g_csr[p1] = s0.y; g_csr[p2] = s0.z; g_csr[p3] = s0.w;
        g_csr[p4] = s1.x; g_csr[p5] = s1.y; g_csr[p6] = s1.z; g_csr[p7] = s1.w;
    } else {
        for (int j = i; j < E; j++) {
            int p = atomicAdd(&g_cursor[dst[j]], 1);
            g_csr[p] = src[j];
        }
    }
}

// ---------------------------------------------------------------------------
// GEMM1: x16 = fp16( (feat * nsrc) @ W1 )   [N,128]x[128,64], FFMA2 inner
// ---------------------------------------------------------------------------
__global__ void __launch_bounds__(256) gemm1_kernel(const float* __restrict__ feat,
                                                    const float* __restrict__ W1, int N) {
    __shared__ float As[64][68];
    __shared__ float Ws[64][64];
    int tx = threadIdx.x & 15, ty = threadIdx.x >> 4;
    int r0 = blockIdx.x * 64;

    ull acc01[4], acc23[4];
    ull zz = f2pack(0.f, 0.f);
#pragma unroll
    for (int i = 0; i < 4; i++) { acc01[i] = zz; acc23[i] = zz; }

    for (int k0 = 0; k0 < FD; k0 += 64) {
        for (int idx = threadIdx.x; idx < 1024; idx += 256) {
            int r = idx >> 4;
            int c4 = idx & 15;
            int row = r0 + r;
            float4 v = make_float4(0.f, 0.f, 0.f, 0.f);
            float s = 0.f;
            if (row < N) {
                v = *(const float4*)(feat + (size_t)row * FD + k0 + c4 * 4);
                s = g_nsrc[row];
            }
            v.x *= s; v.y *= s; v.z *= s; v.w *= s;
            *(float4*)&As[r][c4 * 4] = v;
        }
        for (int idx = threadIdx.x; idx < 1024; idx += 256) {
            ((float4*)Ws)[idx] = ((const float4*)(W1 + (size_t)k0 * HD))[idx];
        }
        __syncthreads();

#pragma unroll
        for (int k = 0; k < 64; k += 2) {
            float2 a0 = *(float2*)&As[ty * 4 + 0][k];
            float2 a1 = *(float2*)&As[ty * 4 + 1][k];
            float2 a2 = *(float2*)&As[ty * 4 + 2][k];
            float2 a3 = *(float2*)&As[ty * 4 + 3][k];
            float4 wA = *(float4*)&Ws[k][tx * 4];
            float4 wB = *(float4*)&Ws[k + 1][tx * 4];
            ull wA01 = f2pack(wA.x, wA.y), wA23 = f2pack(wA.z, wA.w);
            ull wB01 = f2pack(wB.x, wB.y), wB23 = f2pack(wB.z, wB.w);
            ull d;
            d = f2pack(a0.x, a0.x); f2fma(acc01[0], d, wA01); f2fma(acc23[0], d, wA23);
            d = f2pack(a0.y, a0.y); f2fma(acc01[0], d, wB01); f2fma(acc23[0], d, wB23);
            d = f2pack(a1.x, a1.x); f2fma(acc01[1], d, wA01); f2fma(acc23[1], d, wA23);
            d = f2pack(a1.y, a1.y); f2fma(acc01[1], d, wB01); f2fma(acc23[1], d, wB23);
            d = f2pack(a2.x, a2.x); f2fma(acc01[2], d, wA01); f2fma(acc23[2], d, wA23);
            d = f2pack(a2.y, a2.y); f2fma(acc01[2], d, wB01); f2fma(acc23[2], d, wB23);
            d = f2pack(a3.x, a3.x); f2fma(acc01[3], d, wA01); f2fma(acc23[3], d, wA23);
            d = f2pack(a3.y, a3.y); f2fma(acc01[3], d, wB01); f2fma(acc23[3], d, wB23);
        }
        __syncthreads();
    }

#pragma unroll
    for (int i = 0; i < 4; i++) {
        int row = r0 + ty * 4 + i;
        if (row < N) {
            float2 c01 = f2unpack(acc01[i]);
            float2 c23 = f2unpack(acc23[i]);
            __half2 h0 = __floats2half2_rn(c01.x, c01.y);
            __half2 h1 = __floats2half2_rn(c23.x, c23.y);
            uint2 pk;
            pk.x = *(unsigned*)&h0;
            pk.y = *(unsigned*)&h1;
            *(uint2*)(g_x16 + (size_t)row * HD + tx * 4) = pk;
        }
    }
}

// ---------------------------------------------------------------------------
// Shuffle-batched gather core (~1 LDG per edge)
// ---------------------------------------------------------------------------
__device__ __forceinline__ void gather_row(const __half* __restrict__ X,
                                           int beg, int end, int lane,
                                           float& ax, float& ay) {
    ax = 0.f; ay = 0.f;
    int j = beg;
    for (; j + 32 <= end; j += 32) {
        int s = g_csr[j + lane];
#pragma unroll
        for (int t = 0; t < 32; t += 4) {
            int r0 = __shfl_sync(0xffffffffu, s, t + 0);
            int r1 = __shfl_sync(0xffffffffu, s, t + 1);
            int r2 = __shfl_sync(0xffffffffu, s, t + 2);
            int r3 = __shfl_sync(0xffffffffu, s, t + 3);
            float2 v0 = __half22float2(*(const __half2*)(X + (size_t)r0 * HD + lane * 2));
            float2 v1 = __half22float2(*(const __half2*)(X + (size_t)r1 * HD + lane * 2));
            float2 v2 = __half22float2(*(const __half2*)(X + (size_t)r2 * HD + lane * 2));
            float2 v3 = __half22float2(*(const __half2*)(X + (size_t)r3 * HD + lane * 2));
            ax += (v0.x + v1.x) + (v2.x + v3.x);
            ay += (v0.y + v1.y) + (v2.y + v3.y);
        }
    }
    int rem = end - j;
    if (rem > 0) {
        int s = (lane < rem) ? g_csr[j + lane] : 0;
        int t = 0;
        for (; t + 4 <= rem; t += 4) {
            int r0 = __shfl_sync(0xffffffffu, s, t + 0);
            int r1 = __shfl_sync(0xffffffffu, s, t + 1);
            int r2 = __shfl_sync(0xffffffffu, s, t + 2);
            int r3 = __shfl_sync(0xffffffffu, s, t + 3);
            float2 v0 = __half22float2(*(const __half2*)(X + (size_t)r0 * HD + lane * 2));
            float2 v1 = __half22float2(*(const __half2*)(X + (size_t)r1 * HD + lane * 2));
            float2 v2 = __half22float2(*(const __half2*)(X + (size_t)r2 * HD + lane * 2));
            float2 v3 = __half22float2(*(const __half2*)(X + (size_t)r3 * HD + lane * 2));
            ax += (v0.x + v1.x) + (v2.x + v3.x);
            ay += (v0.y + v1.y) + (v2.y + v3.y);
        }
        for (; t < rem; t++) {
            int r = __shfl_sync(0xffffffffu, s, t);
            float2 v = __half22float2(*(const __half2*)(X + (size_t)r * HD + lane * 2));
            ax += v.x; ay += v.y;
        }
    }
}

__global__ void __launch_bounds__(256) gather1_kernel(const float* __restrict__ b1, int N) {
    int warp = (blockIdx.x * blockDim.x + threadIdx.x) >> 5;
    int lane = threadIdx.x & 31;
    if (warp >= N) return;
    int beg = g_off[warp];
    int end = beg + g_cnt[NN + warp];

    float ax, ay;
    gather_row(g_x16, beg, end, lane, ax, ay);

    float nd = g_ndst[warp];
    float ns = g_nsrc[warp];
    float2 b = *(const float2*)(b1 + lane * 2);
    float ox = fmaxf(ax * nd + b.x, 0.f) * ns;
    float oy = fmaxf(ay * nd + b.y, 0.f) * ns;
    *(__half2*)(g_y16 + (size_t)warp * HD + lane * 2) = __floats2half2_rn(ox, oy);
}

// ---------------------------------------------------------------------------
// Fused gather2 + final dual-GEMM:
//   a[n] = (sum y16[s]) * ndst[n]  (gathered into smem As)
//   z = (a@W_mu + b_mu) + noise * exp(a@W_sig + b_sig)
// ---------------------------------------------------------------------------
__global__ void __launch_bounds__(256) final_fused_kernel(const float* __restrict__ noise,
                                                          const float* __restrict__ W_mu,
                                                          const float* __restrict__ b_mu,
                                                          const float* __restrict__ W_sig,
                                                          const float* __restrict__ b_sig,
                                                          float* __restrict__ out, int N) {
    __shared__ float As[64][68];
    __shared__ float Wc[32][128];
    int tx = threadIdx.x & 15, ty = threadIdx.x >> 4;
    int wid = threadIdx.x >> 5, lane = threadIdx.x & 31;
    int r0 = blockIdx.x * 64;

    // Gather phase: warp w gathers rows [w*8, w*8+8)
#pragma unroll
    for (int rr = 0; rr < 8; rr++) {
        int r = wid * 8 + rr;
        int node = r0 + r;
        float ax = 0.f, ay = 0.f;
        if (node < N) {
            int beg = g_off[node];
            int end = beg + g_cnt[NN + node];
            gather_row(g_y16, beg, end, lane, ax, ay);
            float nd = g_ndst[node];
            ax *= nd; ay *= nd;
        }
        *(float2*)&As[r][lane * 2] = make_float2(ax, ay);
    }
    __syncthreads();

    ull am01[4], am23[4], as01[4], as23[4];
    ull zz = f2pack(0.f, 0.f);
#pragma unroll
    for (int i = 0; i < 4; i++) { am01[i] = zz; am23[i] = zz; as01[i] = zz; as23[i] = zz; }

    for (int k0 = 0; k0 < HD; k0 += 32) {
        for (int idx = threadIdx.x; idx < 1024; idx += 256) {
            int k = idx >> 5;
            int c4 = idx & 31;
            if (c4 < 16) {
                *(float4*)&Wc[k][c4 * 4] = *(const float4*)(W_mu + (size_t)(k0 + k) * HD + c4 * 4);
            } else {
                *(float4*)&Wc[k][64 + (c4 - 16) * 4] =
                    *(const float4*)(W_sig + (size_t)(k0 + k) * HD + (c4 - 16) * 4);
            }
        }
        __syncthreads();

#pragma unroll
        for (int k = 0; k < 32; k += 2) {
            float2 a0 = *(float2*)&As[ty * 4 + 0][k0 + k];
            float2 a1 = *(float2*)&As[ty * 4 + 1][k0 + k];
            float2 a2 = *(float2*)&As[ty * 4 + 2][k0 + k];
            float2 a3 = *(float2*)&As[ty * 4 + 3][k0 + k];
            float4 wmA = *(float4*)&Wc[k][tx * 4];
            float4 wsA = *(float4*)&Wc[k][64 + tx * 4];
            float4 wmB = *(float4*)&Wc[k + 1][tx * 4];
            float4 wsB = *(float4*)&Wc[k + 1][64 + tx * 4];
            ull wmA01 = f2pack(wmA.x, wmA.y), wmA23 = f2pack(wmA.z, wmA.w);
            ull wsA01 = f2pack(wsA.x, wsA.y), wsA23 = f2pack(wsA.z, wsA.w);
            ull wmB01 = f2pack(wmB.x, wmB.y), wmB23 = f2pack(wmB.z, wmB.w);
            ull wsB01 = f2pack(wsB.x, wsB.y), wsB23 = f2pack(wsB.z, wsB.w);
            ull d;
            d = f2pack(a0.x, a0.x);
            f2fma(am01[0], d, wmA01); f2fma(am23[0], d, wmA23);
            f2fma(as01[0], d, wsA01); f2fma(as23[0], d, wsA23);
            d = f2pack(a0.y, a0.y);
            f2fma(am01[0], d, wmB01); f2fma(am23[0], d, wmB23);
            f2fma(as01[0], d, wsB01); f2fma(as23[0], d, wsB23);
            d = f2pack(a1.x, a1.x);
            f2fma(am01[1], d, wmA01); f2fma(am23[1], d, wmA23);
            f2fma(as01[1], d, wsA01); f2fma(as23[1], d, wsA23);
            d = f2pack(a1.y, a1.y);
            f2fma(am01[1], d, wmB01); f2fma(am23[1], d, wmB23);
            f2fma(as01[1], d, wsB01); f2fma(as23[1], d, wsB23);
            d = f2pack(a2.x, a2.x);
            f2fma(am01[2], d, wmA01); f2fma(am23[2], d, wmA23);
            f2fma(as01[2], d, wsA01); f2fma(as23[2], d, wsA23);
            d = f2pack(a2.y, a2.y);
            f2fma(am01[2], d, wmB01); f2fma(am23[2], d, wmB23);
            f2fma(as01[2], d, wsB01); f2fma(as23[2], d, wsB23);
            d = f2pack(a3.x, a3.x);
            f2fma(am01[3], d, wmA01); f2fma(am23[3], d, wmA23);
            f2fma(as01[3], d, wsA01); f2fma(as23[3], d, wsA23);
            d = f2pack(a3.y, a3.y);
            f2fma(am01[3], d, wmB01); f2fma(am23[3], d, wmB23);
            f2fma(as01[3], d, wsB01); f2fma(as23[3], d, wsB23);
        }
        __syncthreads();
    }

    float4 bm = *(const float4*)(b_mu + tx * 4);
    float4 bs = *(const float4*)(b_sig + tx * 4);

#pragma unroll
    for (int i = 0; i < 4; i++) {
        int row = r0 + ty * 4 + i;
        if (row < N) {
            float2 m01 = f2unpack(am01[i]);
            float2 m23 = f2unpack(am23[i]);
            float2 s01 = f2unpack(as01[i]);
            float2 s23 = f2unpack(as23[i]);
            float4 nz = *(const float4*)(noise + (size_t)row * HD + tx * 4);
            float4 o;
            o.x = (m01.x + bm.x) + nz.x * expf(s01.x + bs.x);
            o.y = (m01.y + bm.y) + nz.y * expf(s01.y + bs.y);
            o.z = (m23.x + bm.z) + nz.z * expf(s23.x + bs.z);
            o.w = (m23.y + bm.w) + nz.w * expf(s23.y + bs.w);
            *(float4*)(out + (size_t)row * HD + tx * 4) = o;
        }
    }
}

// ---------------------------------------------------------------------------
// Launch
// ---------------------------------------------------------------------------
static cudaStream_t s2 = nullptr;
static cudaEvent_t  evScan = nullptr, evGemm = nullptr;

extern "C" void kernel_launch(void* const* d_in, const int* in_sizes, int n_in,
                              void* d_out, int out_size) {
    const float* feat  = (const float*)d_in[0];
    const int*   src   = (const int*)d_in[1];
    const int*   dst   = (const int*)d_in[2];
    const float* noise = (const float*)d_in[3];
    const float* W1    = (const float*)d_in[4];
    const float* b1    = (const float*)d_in[5];
    const float* W_mu  = (const float*)d_in[6];
    const float* b_mu  = (const float*)d_in[7];
    const float* W_sig = (const float*)d_in[8];
    const float* b_sig = (const float*)d_in[9];

    int N = in_sizes[0] / FD;
    int E = in_sizes[1];

    if (s2 == nullptr) {
        cudaStreamCreateWithFlags(&s2, cudaStreamNonBlocking);
        cudaEventCreateWithFlags(&evScan, cudaEventDisableTiming);
        cudaEventCreateWithFlags(&evGemm, cudaEventDisableTiming);
    }

    void* p_cnt;
    cudaGetSymbolAddress(&p_cnt, g_cnt);
    cudaMemsetAsync(p_cnt, 0, sizeof(int) * (2 * NN + 32));

    deg_kernel<<<(E / 8 + 255) / 256, 256>>>(src, dst, E);
    scan_norm_kernel<<<(N + 255) / 256, 256>>>(N);
    cudaEventRecord(evScan, 0);

    // gemm1 (needs nsrc only) overlaps with fill on stream 2
    cudaStreamWaitEvent(s2, evScan, 0);
    gemm1_kernel<<<(N + 63) / 64, 256, 0, s2>>>(feat, W1, N);
    cudaEventRecord(evGemm, s2);

    fill_kernel<<<(E / 8 + 255) / 256, 256>>>(src, dst, E);
    cudaStreamWaitEvent(0, evGemm, 0);

    int gblocks = (N * 32 + 255) / 256;
    gather1_kernel<<<gblocks, 256>>>(b1, N);

    final_fused_kernel<<<(N + 63) / 64, 256>>>(noise, W_mu, b_mu, W_sig, b_sig,
                                               (float*)d_out, N);
}

// round 6
// speedup vs baseline: 1.0448x; 1.0448x over previous
#include <cuda_runtime.h>
#include <cuda_fp16.h>
#include <math.h>

#define NN 100000
#define EE 1600000
#define FD 128
#define HD 64

// Scratch (device globals)
__device__ int    g_cnt[2 * NN + 32];       // [0..NN)=out(src), [NN..2NN)=in(dst), [2NN]=ticket
__device__ float  g_nsrc[NN];
__device__ float  g_ndst[NN];
__device__ int    g_off[NN];
__device__ int    g_cursor[NN];
__device__ int    g_csr[EE];
__device__ __half g_x16[(size_t)NN * HD];
__device__ __half g_y16[(size_t)NN * HD];
__device__ float  g_a2[(size_t)NN * HD];

// ---------------------------------------------------------------------------
// Degree kernels (split: dst on main stream, src on side stream)
// ---------------------------------------------------------------------------
__global__ void deg_dst_kernel(const int* __restrict__ dst, int E) {
    int i = (blockIdx.x * blockDim.x + threadIdx.x) * 4;
    if (i + 4 <= E) {
        int4 d = *(const int4*)(dst + i);
        atomicAdd(&g_cnt[NN + d.x], 1); atomicAdd(&g_cnt[NN + d.y], 1);
        atomicAdd(&g_cnt[NN + d.z], 1); atomicAdd(&g_cnt[NN + d.w], 1);
    } else {
        for (int j = i; j < E; j++) atomicAdd(&g_cnt[NN + dst[j]], 1);
    }
}

__global__ void deg_src_kernel(const int* __restrict__ src, int E) {
    int i = (blockIdx.x * blockDim.x + threadIdx.x) * 4;
    if (i + 4 <= E) {
        int4 s = *(const int4*)(src + i);
        atomicAdd(&g_cnt[s.x], 1); atomicAdd(&g_cnt[s.y], 1);
        atomicAdd(&g_cnt[s.z], 1); atomicAdd(&g_cnt[s.w], 1);
    } else {
        for (int j = i; j < E; j++) atomicAdd(&g_cnt[src[j]], 1);
    }
}

__global__ void norm_src_kernel(int N) {
    int i = blockIdx.x * blockDim.x + threadIdx.x;
    if (i < N) g_nsrc[i] = rsqrtf(fmaxf((float)g_cnt[i], 1.0f));
}

// ---------------------------------------------------------------------------
// Scan (in-degree) + ndst. Segments disjoint/unordered via atomic ticket.
// ---------------------------------------------------------------------------
__global__ void __launch_bounds__(256) scan_kernel(int N) {
    __shared__ int wsum[8];
    __shared__ int sbase;
    int i = blockIdx.x * 256 + threadIdx.x;
    int lane = threadIdx.x & 31, wid = threadIdx.x >> 5;

    int cin = (i < N) ? g_cnt[NN + i] : 0;
    int x = cin;
#pragma unroll
    for (int o = 1; o < 32; o <<= 1) {
        int n = __shfl_up_sync(0xffffffffu, x, o);
        if (lane >= o) x += n;
    }
    if (lane == 31) wsum[wid] = x;
    __syncthreads();
    if (threadIdx.x == 0) {
        int run = 0;
#pragma unroll
        for (int w = 0; w < 8; w++) { run += wsum[w]; wsum[w] = run; }
        sbase = atomicAdd(&g_cnt[2 * NN], run);
    }
    __syncthreads();
    int excl = x - cin + (wid > 0 ? wsum[wid - 1] : 0) + sbase;
    if (i < N) {
        g_off[i] = excl;
        g_cursor[i] = excl;
        g_ndst[i] = rsqrtf(fmaxf((float)cin, 1.0f));
    }
}

// ---------------------------------------------------------------------------
// Fill CSR: 1 edge per thread (max resident-atomic MLP; R4-proven)
// ---------------------------------------------------------------------------
__global__ void fill_kernel(const int* __restrict__ src, const int* __restrict__ dst, int E) {
    int i = blockIdx.x * blockDim.x + threadIdx.x;
    if (i < E) {
        int p = atomicAdd(&g_cursor[dst[i]], 1);
        g_csr[p] = src[i];
    }
}

// ---------------------------------------------------------------------------
// GEMM1: x16 = fp16( (feat * nsrc) @ W1 )  (R4-proven fp32 version)
// ---------------------------------------------------------------------------
__global__ void __launch_bounds__(256) gemm1_kernel(const float* __restrict__ feat,
                                                    const float* __restrict__ W1, int N) {
    __shared__ float As[64][68];
    __shared__ float Ws[64][64];
    int tx = threadIdx.x & 15, ty = threadIdx.x >> 4;
    int r0 = blockIdx.x * 64;

    float acc[4][4] = {};

    for (int k0 = 0; k0 < FD; k0 += 64) {
        for (int idx = threadIdx.x; idx < 1024; idx += 256) {
            int r = idx >> 4;
            int c4 = idx & 15;
            int row = r0 + r;
            float4 v = make_float4(0.f, 0.f, 0.f, 0.f);
            float s = 0.f;
            if (row < N) {
                v = *(const float4*)(feat + (size_t)row * FD + k0 + c4 * 4);
                s = g_nsrc[row];
            }
            v.x *= s; v.y *= s; v.z *= s; v.w *= s;
            *(float4*)&As[r][c4 * 4] = v;
        }
        for (int idx = threadIdx.x; idx < 1024; idx += 256) {
            ((float4*)Ws)[idx] = ((const float4*)(W1 + (size_t)k0 * HD))[idx];
        }
        __syncthreads();

#pragma unroll
        for (int k = 0; k < 64; k++) {
            float a0 = As[ty * 4 + 0][k];
            float a1 = As[ty * 4 + 1][k];
            float a2 = As[ty * 4 + 2][k];
            float a3 = As[ty * 4 + 3][k];
            float4 w = *(float4*)&Ws[k][tx * 4];
            acc[0][0] += a0 * w.x; acc[0][1] += a0 * w.y; acc[0][2] += a0 * w.z; acc[0][3] += a0 * w.w;
            acc[1][0] += a1 * w.x; acc[1][1] += a1 * w.y; acc[1][2] += a1 * w.z; acc[1][3] += a1 * w.w;
            acc[2][0] += a2 * w.x; acc[2][1] += a2 * w.y; acc[2][2] += a2 * w.z; acc[2][3] += a2 * w.w;
            acc[3][0] += a3 * w.x; acc[3][1] += a3 * w.y; acc[3][2] += a3 * w.z; acc[3][3] += a3 * w.w;
        }
        __syncthreads();
    }

#pragma unroll
    for (int i = 0; i < 4; i++) {
        int row = r0 + ty * 4 + i;
        if (row < N) {
            __half2 h0 = __floats2half2_rn(acc[i][0], acc[i][1]);
            __half2 h1 = __floats2half2_rn(acc[i][2], acc[i][3]);
            uint2 pk;
            pk.x = *(unsigned*)&h0;
            pk.y = *(unsigned*)&h1;
            *(uint2*)(g_x16 + (size_t)row * HD + tx * 4) = pk;
        }
    }
}

// ---------------------------------------------------------------------------
// Shuffle-batched gather core (~1 LDG per edge) — R4-proven
// ---------------------------------------------------------------------------
__device__ __forceinline__ void gather_row(const __half* __restrict__ X,
                                           int beg, int end, int lane,
                                           float& ax, float& ay) {
    ax = 0.f; ay = 0.f;
    int j = beg;
    for (; j + 32 <= end; j += 32) {
        int s = g_csr[j + lane];
#pragma unroll
        for (int t = 0; t < 32; t += 4) {
            int r0 = __shfl_sync(0xffffffffu, s, t + 0);
            int r1 = __shfl_sync(0xffffffffu, s, t + 1);
            int r2 = __shfl_sync(0xffffffffu, s, t + 2);
            int r3 = __shfl_sync(0xffffffffu, s, t + 3);
            float2 v0 = __half22float2(*(const __half2*)(X + (size_t)r0 * HD + lane * 2));
            float2 v1 = __half22float2(*(const __half2*)(X + (size_t)r1 * HD + lane * 2));
            float2 v2 = __half22float2(*(const __half2*)(X + (size_t)r2 * HD + lane * 2));
            float2 v3 = __half22float2(*(const __half2*)(X + (size_t)r3 * HD + lane * 2));
            ax += (v0.x + v1.x) + (v2.x + v3.x);
            ay += (v0.y + v1.y) + (v2.y + v3.y);
        }
    }
    int rem = end - j;
    if (rem > 0) {
        int s = (lane < rem) ? g_csr[j + lane] : 0;
        int t = 0;
        for (; t + 4 <= rem; t += 4) {
            int r0 = __shfl_sync(0xffffffffu, s, t + 0);
            int r1 = __shfl_sync(0xffffffffu, s, t + 1);
            int r2 = __shfl_sync(0xffffffffu, s, t + 2);
            int r3 = __shfl_sync(0xffffffffu, s, t + 3);
            float2 v0 = __half22float2(*(const __half2*)(X + (size_t)r0 * HD + lane * 2));
            float2 v1 = __half22float2(*(const __half2*)(X + (size_t)r1 * HD + lane * 2));
            float2 v2 = __half22float2(*(const __half2*)(X + (size_t)r2 * HD + lane * 2));
            float2 v3 = __half22float2(*(const __half2*)(X + (size_t)r3 * HD + lane * 2));
            ax += (v0.x + v1.x) + (v2.x + v3.x);
            ay += (v0.y + v1.y) + (v2.y + v3.y);
        }
        for (; t < rem; t++) {
            int r = __shfl_sync(0xffffffffu, s, t);
            float2 v = __half22float2(*(const __half2*)(X + (size_t)r * HD + lane * 2));
            ax += v.x; ay += v.y;
        }
    }
}

__global__ void __launch_bounds__(256) gather1_kernel(const float* __restrict__ b1, int N) {
    int warp = (blockIdx.x * blockDim.x + threadIdx.x) >> 5;
    int lane = threadIdx.x & 31;
    if (warp >= N) return;
    int beg = g_off[warp];
    int end = beg + g_cnt[NN + warp];

    float ax, ay;
    gather_row(g_x16, beg, end, lane, ax, ay);

    float nd = g_ndst[warp];
    float ns = g_nsrc[warp];
    float2 b = *(const float2*)(b1 + lane * 2);
    float ox = fmaxf(ax * nd + b.x, 0.f) * ns;
    float oy = fmaxf(ay * nd + b.y, 0.f) * ns;
    *(__half2*)(g_y16 + (size_t)warp * HD + lane * 2) = __floats2half2_rn(ox, oy);
}

__global__ void __launch_bounds__(256) gather2_kernel(int N) {
    int warp = (blockIdx.x * blockDim.x + threadIdx.x) >> 5;
    int lane = threadIdx.x & 31;
    if (warp >= N) return;
    int beg = g_off[warp];
    int end = beg + g_cnt[NN + warp];

    float ax, ay;
    gather_row(g_y16, beg, end, lane, ax, ay);

    float nd = g_ndst[warp];
    *(float2*)(g_a2 + (size_t)warp * HD + lane * 2) = make_float2(ax * nd, ay * nd);
}

// ---------------------------------------------------------------------------
// Final: z = (a@W_mu + b_mu) + noise * exp(a@W_sig + b_sig), a = g_a2 — R4-proven
// ---------------------------------------------------------------------------
__global__ void __launch_bounds__(256) final_kernel(const float* __restrict__ noise,
                                                    const float* __restrict__ W_mu,
                                                    const float* __restrict__ b_mu,
                                                    const float* __restrict__ W_sig,
                                                    const float* __restrict__ b_sig,
                                                    float* __restrict__ out, int N) {
    __shared__ float As[64][36];
    __shared__ float Wc[32][128];
    int tx = threadIdx.x & 15, ty = threadIdx.x >> 4;
    int r0 = blockIdx.x * 64;

    float am[4][4] = {};
    float asg[4][4] = {};

    for (int k0 = 0; k0 < HD; k0 += 32) {
        for (int idx = threadIdx.x; idx < 512; idx += 256) {
            int r = idx >> 3;
            int c4 = idx & 7;
            int row = r0 + r;
            float4 v = make_float4(0.f, 0.f, 0.f, 0.f);
            if (row < N) v = *(const float4*)(g_a2 + (size_t)row * HD + k0 + c4 * 4);
            *(float4*)&As[r][c4 * 4] = v;
        }
        for (int idx = threadIdx.x; idx < 1024; idx += 256) {
            int k = idx >> 5;
            int c4 = idx & 31;
            if (c4 < 16) {
                *(float4*)&Wc[k][c4 * 4] = *(const float4*)(W_mu + (size_t)(k0 + k) * HD + c4 * 4);
            } else {
                *(float4*)&Wc[k][64 + (c4 - 16) * 4] =
                    *(const float4*)(W_sig + (size_t)(k0 + k) * HD + (c4 - 16) * 4);
            }
        }
        __syncthreads();

#pragma unroll
        for (int k = 0; k < 32; k++) {
            float a0 = As[ty * 4 + 0][k];
            float a1 = As[ty * 4 + 1][k];
            float a2 = As[ty * 4 + 2][k];
            float a3 = As[ty * 4 + 3][k];
            float4 wm = *(float4*)&Wc[k][tx * 4];
            float4 ws = *(float4*)&Wc[k][64 + tx * 4];
            am[0][0] += a0 * wm.x; am[0][1] += a0 * wm.y; am[0][2] += a0 * wm.z; am[0][3] += a0 * wm.w;
            am[1][0] += a1 * wm.x; am[1][1] += a1 * wm.y; am[1][2] += a1 * wm.z; am[1][3] += a1 * wm.w;
            am[2][0] += a2 * wm.x; am[2][1] += a2 * wm.y; am[2][2] += a2 * wm.z; am[2][3] += a2 * wm.w;
            am[3][0] += a3 * wm.x; am[3][1] += a3 * wm.y; am[3][2] += a3 * wm.z; am[3][3] += a3 * wm.w;
            asg[0][0] += a0 * ws.x; asg[0][1] += a0 * ws.y; asg[0][2] += a0 * ws.z; asg[0][3] += a0 * ws.w;
            asg[1][0] += a1 * ws.x; asg[1][1] += a1 * ws.y; asg[1][2] += a1 * ws.z; asg[1][3] += a1 * ws.w;
            asg[2][0] += a2 * ws.x; asg[2][1] += a2 * ws.y; asg[2][2] += a2 * ws.z; asg[2][3] += a2 * ws.w;
            asg[3][0] += a3 * ws.x; asg[3][1] += a3 * ws.y; asg[3][2] += a3 * ws.z; asg[3][3] += a3 * ws.w;
        }
        __syncthreads();
    }

    float4 bm = *(const float4*)(b_mu + tx * 4);
    float4 bs = *(const float4*)(b_sig + tx * 4);

#pragma unroll
    for (int i = 0; i < 4; i++) {
        int row = r0 + ty * 4 + i;
        if (row < N) {
            float4 nz = *(const float4*)(noise + (size_t)row * HD + tx * 4);
            float4 o;
            o.x = (am[i][0] + bm.x) + nz.x * expf(asg[i][0] + bs.x);
            o.y = (am[i][1] + bm.y) + nz.y * expf(asg[i][1] + bs.y);
            o.z = (am[i][2] + bm.z) + nz.z * expf(asg[i][2] + bs.z);
            o.w = (am[i][3] + bm.w) + nz.w * expf(asg[i][3] + bs.w);
            *(float4*)(out + (size_t)row * HD + tx * 4) = o;
        }
    }
}

// ---------------------------------------------------------------------------
// Launch: dual-stream setup
//   s1(=0): memset(in+ticket) -> deg_dst -> scan -> fill ----\
//   s2:     memset(out)       -> deg_src -> norm -> gemm1 ---+-> gather1 -> gather2 -> final
// ---------------------------------------------------------------------------
static cudaStream_t s2 = nullptr;
static cudaEvent_t  evRoot = nullptr, evGemm = nullptr;

extern "C" void kernel_launch(void* const* d_in, const int* in_sizes, int n_in,
                              void* d_out, int out_size) {
    const float* feat  = (const float*)d_in[0];
    const int*   src   = (const int*)d_in[1];
    const int*   dst   = (const int*)d_in[2];
    const float* noise = (const float*)d_in[3];
    const float* W1    = (const float*)d_in[4];
    const float* b1    = (const float*)d_in[5];
    const float* W_mu  = (const float*)d_in[6];
    const float* b_mu  = (const float*)d_in[7];
    const float* W_sig = (const float*)d_in[8];
    const float* b_sig = (const float*)d_in[9];

    int N = in_sizes[0] / FD;
    int E = in_sizes[1];

    if (s2 == nullptr) {
        cudaStreamCreateWithFlags(&s2, cudaStreamNonBlocking);
        cudaEventCreateWithFlags(&evRoot, cudaEventDisableTiming);
        cudaEventCreateWithFlags(&evGemm, cudaEventDisableTiming);
    }

    char* p_cnt;
    cudaGetSymbolAddress((void**)&p_cnt, g_cnt);

    // Fork s2 from the capture stream
    cudaEventRecord(evRoot, 0);
    cudaStreamWaitEvent(s2, evRoot, 0);

    // s1: in-degree path
    cudaMemsetAsync(p_cnt + sizeof(int) * NN, 0, sizeof(int) * (NN + 32), 0);
    deg_dst_kernel<<<(E / 4 + 255) / 256, 256>>>(dst, E);
    scan_kernel<<<(N + 255) / 256, 256>>>(N);
    fill_kernel<<<(E + 255) / 256, 256>>>(src, dst, E);

    // s2: out-degree path + gemm1
    cudaMemsetAsync(p_cnt, 0, sizeof(int) * NN, s2);
    deg_src_kernel<<<(E / 4 + 255) / 256, 256, 0, s2>>>(src, E);
    norm_src_kernel<<<(N + 255) / 256, 256, 0, s2>>>(N);
    gemm1_kernel<<<(N + 63) / 64, 256, 0, s2>>>(feat, W1, N);
    cudaEventRecord(evGemm, s2);

    // Join: gather1 needs fill (s1) + x16/nsrc (s2)
    cudaStreamWaitEvent(0, evGemm, 0);

    int gblocks = (N * 32 + 255) / 256;
    gather1_kernel<<<gblocks, 256>>>(b1, N);
    gather2_kernel<<<gblocks, 256>>>(N);

    final_kernel<<<(N + 63) / 64, 256>>>(noise, W_mu, b_mu, W_sig, b_sig,
                                         (float*)d_out, N);
}